// round 2
// baseline (speedup 1.0000x reference)
#include <cuda_runtime.h>
#include <math.h>

#define CCH   128
#define HW    262144          // 512*512
#define NB    256

// 128MB key scratch + loss accumulator (static __device__ — allocation-free)
__device__ unsigned int g_keys[(size_t)CCH * HW];
__device__ double g_loss;

__device__ __forceinline__ unsigned int fkey(float x) {
    unsigned int u = __float_as_uint(x);
    return (u & 0x80000000u) ? ~u : (u | 0x80000000u);
}
__device__ __forceinline__ float dkey(unsigned int k) {
    return __uint_as_float((k & 0x80000000u) ? (k & 0x7fffffffu) : ~k);
}

__global__ void init_kernel() { g_loss = 0.0; }

__global__ void finish_kernel(float* out) {
    out[0] = (float)(g_loss * (0.01 / ((double)CCH * (double)HW)));
}

// shared memory layout (u32 units):
//  HIST      [0,      32768)   packed u16x2 histogram (64K bins / 256x256 refinement)
//  cutP      [32768,  33024)
//  cutR      [33024,  33280)
//  cutS      [33280,  33536)
//  uniq      [33536,  33792)   (also cdf float temp)
//  sgrp      [33792,  34049)
//  th        [34049,  34305)   (also K_j temp)
//  chist     [34305,  34561)
//  red       [34561,  34633)   reduction scratch + scalars
#define SMEM_WORDS 34633
#define SMEM_BYTES (SMEM_WORDS * 4)

extern __shared__ unsigned int smem[];

__global__ void __launch_bounds__(1024, 1)
main_kernel(const float* __restrict__ input, const float* __restrict__ mask,
            const float* __restrict__ thist, const float* __restrict__ tmin_,
            const float* __restrict__ tmax_, float* __restrict__ out)
{
    unsigned int* HIST  = smem;
    unsigned int* cutP  = smem + 32768;
    unsigned int* cutR  = cutP + 256;
    unsigned int* cutS  = cutR + 256;
    unsigned int* uniq  = cutS + 256;
    unsigned int* sgrp  = uniq + 256;   // 257 entries
    unsigned int* th    = sgrp + 257;
    unsigned int* chist = th + 256;
    unsigned int* red   = chist + 256;  // 72 entries

    const int c   = blockIdx.x;
    const int tid = threadIdx.x;
    const int NT  = 1024;

    // zero histograms
    for (int i = tid; i < 32768; i += NT) HIST[i] = 0;
    if (tid < 256) chist[tid] = 0;
    __syncthreads();

    // ---------------- Phase 0: keys + min/max + 16-bit histogram ----------------
    {
        const float4* in4 = (const float4*)(input + (size_t)c * HW);
        const float4* mk4 = (const float4*)mask;
        uint4* key4 = (uint4*)(g_keys + (size_t)c * HW);
        unsigned int kmin = 0xffffffffu, kmax = 0u;

        for (int i = tid; i < HW / 4; i += NT) {
            float4 a = in4[i];
            float4 m = mk4[i];
            uint4 k;
            k.x = fkey(a.x * m.x);
            k.y = fkey(a.y * m.y);
            k.z = fkey(a.z * m.z);
            k.w = fkey(a.w * m.w);
            key4[i] = k;
            unsigned int kk;
            kk = k.x; kmin = min(kmin, kk); kmax = max(kmax, kk);
            { unsigned b = kk >> 16; atomicAdd(&HIST[b >> 1], (b & 1) ? 65536u : 1u); }
            kk = k.y; kmin = min(kmin, kk); kmax = max(kmax, kk);
            { unsigned b = kk >> 16; atomicAdd(&HIST[b >> 1], (b & 1) ? 65536u : 1u); }
            kk = k.z; kmin = min(kmin, kk); kmax = max(kmax, kk);
            { unsigned b = kk >> 16; atomicAdd(&HIST[b >> 1], (b & 1) ? 65536u : 1u); }
            kk = k.w; kmin = min(kmin, kk); kmax = max(kmax, kk);
            { unsigned b = kk >> 16; atomicAdd(&HIST[b >> 1], (b & 1) ? 65536u : 1u); }
        }
        // block reduce min/max
        #pragma unroll
        for (int off = 16; off; off >>= 1) {
            kmin = min(kmin, __shfl_down_sync(0xffffffffu, kmin, off));
            kmax = max(kmax, __shfl_down_sync(0xffffffffu, kmax, off));
        }
        if ((tid & 31) == 0) { red[tid >> 5] = kmin; red[32 + (tid >> 5)] = kmax; }
    }
    __syncthreads();
    if (tid == 0) {
        unsigned mn = red[0], mx = red[32];
        for (int w = 1; w < 32; w++) { mn = min(mn, red[w]); mx = max(mx, red[32 + w]); }
        red[64] = mn; red[65] = mx;
    }

    // ---------------- Phase 1: target CDF -> K_j (thread 0, sequential f32) -----
    if (tid == 0) {
        float* cdf = (float*)uniq;
        float s = 0.0f;
        for (int j = 0; j < 256; j++) { s += thist[c * 256 + j]; cdf[j] = s; }
        float tot = s;
        for (int j = 0; j < 256; j++) {
            float t = (cdf[j] / tot) * 262144.0f;
            float f = floorf(t);
            if (f < 0.0f) f = 0.0f;
            if (f > 262144.0f) f = 262144.0f;
            th[j] = (unsigned)f;      // K_j stored temporarily in th[]
        }
    }
    __syncthreads();

    // ---------------- Phase 2: locate cut bins in 16-bit histogram --------------
    if (tid < 256) {
        unsigned s = 0;
        for (int w = 0; w < 128; w++) {
            unsigned v = HIST[tid * 128 + w];
            s += (v & 0xffffu) + (v >> 16);
        }
        sgrp[tid] = s;
    }
    __syncthreads();
    if (tid == 0) {
        unsigned acc = 0;
        for (int g = 0; g < 256; g++) { unsigned t = sgrp[g]; sgrp[g] = acc; acc += t; }
        sgrp[256] = acc;
    }
    __syncthreads();
    if (tid < 256) {
        unsigned k = th[tid];   // K_j
        if (k == 0) {
            cutP[tid] = 0xffffffffu; cutR[tid] = 0;
        } else {
            int lo = 0, hi = 255;                   // largest g with sgrp[g] < k
            while (lo < hi) { int mid = (lo + hi + 1) >> 1; if (sgrp[mid] < k) lo = mid; else hi = mid - 1; }
            unsigned acc = sgrp[lo];
            int bin = lo * 256;
            for (;; bin++) {
                unsigned w = HIST[bin >> 1];
                unsigned cnt = (bin & 1) ? (w >> 16) : (w & 0xffffu);
                if (acc + cnt >= k) break;
                acc += cnt;
            }
            cutP[tid] = (unsigned)bin;
            cutR[tid] = k - acc;
        }
    }
    __syncthreads();

    // ---------------- Phase 3: two 8-bit refinement rounds -----------------------
    for (int r = 0; r < 2; r++) {
        const int shiftP = (r == 0) ? 16 : 8;
        const int shiftS = (r == 0) ? 8 : 0;

        if (tid == 0) {          // unique (sorted: order stats monotone) prefix list
            int n = 0; unsigned prev = 0xffffffffu;
            for (int j = 0; j < 256; j++) {
                unsigned p = cutP[j];
                if (p != 0xffffffffu) {
                    if (n == 0 || p != prev) { uniq[n] = p; prev = p; n++; }
                    cutS[j] = (unsigned)(n - 1);
                }
            }
            red[66] = (unsigned)n;
        }
        __syncthreads();
        const int nU = (int)red[66];
        for (int i = tid; i < 32768; i += NT) HIST[i] = 0;
        __syncthreads();

        if (nU > 0) {
            const uint4* k4 = (const uint4*)(g_keys + (size_t)c * HW);
            for (int i = tid; i < HW / 4; i += NT) {
                uint4 kk = k4[i];
                #pragma unroll
                for (int e = 0; e < 4; e++) {
                    unsigned key = (e == 0) ? kk.x : (e == 1) ? kk.y : (e == 2) ? kk.z : kk.w;
                    unsigned p = key >> shiftP;
                    int lo = 0, hi = nU;
                    while (lo < hi) { int mid = (lo + hi) >> 1; if (uniq[mid] < p) lo = mid + 1; else hi = mid; }
                    if (lo < nU && uniq[lo] == p) {
                        unsigned sub = (key >> shiftS) & 0xffu;
                        unsigned idx = (unsigned)lo * 256u + sub;
                        atomicAdd(&HIST[idx >> 1], (idx & 1) ? 65536u : 1u);
                    }
                }
            }
        }
        __syncthreads();

        if (tid < 256 && cutP[tid] != 0xffffffffu) {
            unsigned s = cutS[tid], k = cutR[tid], acc = 0;
            unsigned base = s * 256u;
            int sub = 0;
            for (;; sub++) {
                unsigned idx = base + (unsigned)sub;
                unsigned w = HIST[idx >> 1];
                unsigned cnt = (idx & 1) ? (w >> 16) : (w & 0xffffu);
                if (acc + cnt >= k) break;
                acc += cnt;
            }
            cutP[tid] = (cutP[tid] << 8) | (unsigned)sub;
            cutR[tid] = k - acc;
        }
        __syncthreads();
    }

    // final thresholds (sorted nondecreasing: K_j nondecreasing)
    if (tid < 256) th[tid] = (cutP[tid] == 0xffffffffu) ? 0u : cutP[tid];
    __syncthreads();

    // ---------------- Phase 4: cur_hist + matched + loss -------------------------
    {
        const float mn = dkey(red[64]);
        const float mx = dkey(red[65]);
        const float dd = fmaxf(mx - mn, 1e-8f);
        const float tmn = tmin_[c];
        const float scl = tmax_[c] - tmn;
        float acc = 0.0f;

        const uint4* k4 = (const uint4*)(g_keys + (size_t)c * HW);
        for (int i = tid; i < HW / 4; i += NT) {
            uint4 kk = k4[i];
            #pragma unroll
            for (int e = 0; e < 4; e++) {
                unsigned key = (e == 0) ? kk.x : (e == 1) ? kk.y : (e == 2) ? kk.z : kk.w;
                float v = dkey(key);
                // current histogram (exact counts)
                float u = (v - mn) / dd;
                int b = (int)(u * 255.0f);
                b = min(max(b, 0), 255);
                atomicAdd(&chist[b], 1u);
                // matched bin = #{th < key}
                int lo = 0, hi = 256;
                while (lo < hi) { int mid = (lo + hi) >> 1; if (th[mid] < key) lo = mid + 1; else hi = mid; }
                int bm = min(lo, 255);
                float tgt = ((float)bm / 255.0f) * scl + tmn;
                float df = v - tgt;
                acc += df * df;
            }
        }
        // block reduce loss partial
        #pragma unroll
        for (int off = 16; off; off >>= 1)
            acc += __shfl_down_sync(0xffffffffu, acc, off);
        __syncthreads();
        if ((tid & 31) == 0) ((float*)red)[tid >> 5] = acc;
        __syncthreads();
        if (tid == 0) {
            float s = 0.0f;
            for (int w = 0; w < 32; w++) s += ((float*)red)[w];
            atomicAdd(&g_loss, (double)s);
        }

        // outputs: [0]=loss, [1..32769)=cur_hist, then cur_min, cur_max
        if (tid < 256) out[1 + c * 256 + tid] = (float)chist[tid];
        if (tid == 0) {
            out[1 + 32768 + c]       = mn;
            out[1 + 32768 + 128 + c] = mx;
        }
    }
}

extern "C" void kernel_launch(void* const* d_in, const int* in_sizes, int n_in,
                              void* d_out, int out_size)
{
    const float* input = (const float*)d_in[0];
    const float* mask  = (const float*)d_in[1];
    const float* thist = (const float*)d_in[2];
    const float* tmn   = (const float*)d_in[3];
    const float* tmx   = (const float*)d_in[4];
    float* out = (float*)d_out;

    cudaFuncSetAttribute(main_kernel, cudaFuncAttributeMaxDynamicSharedMemorySize, SMEM_BYTES);

    init_kernel<<<1, 1>>>();
    main_kernel<<<CCH, 1024, SMEM_BYTES>>>(input, mask, thist, tmn, tmx, out);
    finish_kernel<<<1, 1>>>(out);
}

// round 6
// speedup vs baseline: 1.3918x; 1.3918x over previous
#include <cuda_runtime.h>
#include <math.h>

#define CCH 128
#define HW  262144          // 512*512
#define NT  1024

// candidate scratch (static __device__, allocation-free) + loss accumulator
__device__ unsigned int g_cand[(size_t)CCH * HW];
__device__ double g_loss;

__device__ __forceinline__ unsigned int fkey(float x) {
    unsigned int u = __float_as_uint(x);
    return (u & 0x80000000u) ? ~u : (u | 0x80000000u);
}
__device__ __forceinline__ float dkey(unsigned int k) {
    return __uint_as_float((k & 0x80000000u) ? (k & 0x7fffffffu) : ~k);
}
// reference binning: b = clip(int32((v-mn)/dd * 255), 0, 255); monotone in key
__device__ __forceinline__ int binf(unsigned int k, float mn, float dd) {
    float v = dkey(k);
    float u = (v - mn) / dd;
    int b = (int)(u * 255.0f);
    return b < 0 ? 0 : (b > 255 ? 255 : b);
}

__global__ void init_kernel() { g_loss = 0.0; }
__global__ void finish_kernel(float* out) {
    out[0] = (float)(g_loss * (0.01 / ((double)CCH * (double)HW)));
}

// shared memory layout (u32 words)
#define SMEM_WORDS 45906
#define SMEM_BYTES (SMEM_WORDS * 4)

__global__ void __launch_bounds__(1024, 1)
main_kernel(const float* __restrict__ input, const float* __restrict__ mask,
            const float* __restrict__ thist, const float* __restrict__ tmin_,
            const float* __restrict__ tmax_, float* __restrict__ out)
{
    extern __shared__ unsigned int smem[];
    unsigned int* HIST   = smem;              // 32768: u16x2 hist -> slot16 -> tb16
    unsigned int* WH     = smem + 32768;      // 8192: 32 warps x 256 select hist
    unsigned int* cutBin = WH + 8192;         // 256
    unsigned int* cutR   = cutBin + 256;      // 256
    unsigned int* cutSlot= cutR + 256;        // 256
    unsigned int* thA    = cutSlot + 256;     // 256 threshold keys
    unsigned int* kbA    = thA + 256;         // 256 boundary keys (1..255; 0=sentinel)
    unsigned int* bSlot  = kbA + 256;         // 256
    unsigned int* bPre   = bSlot + 256;       // 256 (#keys with prefix < boundary prefix)
    unsigned int* rankA  = bPre + 256;        // 257
    unsigned int* uniqB  = rankA + 257;       // 512 active bins (sorted)
    unsigned int* segOff = uniqB + 512;       // 512
    unsigned int* segLen = segOff + 512;      // 512
    unsigned int* cursor = segLen + 512;      // 512
    unsigned int* sgrp   = cursor + 512;      // 257 group prefix sums
    float*        tgtT   = (float*)(sgrp + 257); // 256 (also cdf temp)
    unsigned int* Karr   = (unsigned int*)(tgtT + 256); // 256
    unsigned int* red    = Karr + 256;        // 80

    const int c   = blockIdx.x;
    const int tid = threadIdx.x;
    const int lane = tid & 31;
    const int wz   = tid >> 5;
    const float4* in4 = (const float4*)(input + (size_t)c * HW);
    const float4* mk4 = (const float4*)mask;
    unsigned int* candC = g_cand + (size_t)c * HW;

    for (int i = tid; i < 32768; i += NT) HIST[i] = 0;
    __syncthreads();

    // ---------- Pass 1: min/max + 16-bit-prefix histogram ----------
    {
        unsigned kmin = 0xffffffffu, kmax = 0u;
        for (int i = tid; i < HW / 4; i += NT) {
            float4 a = in4[i], m = mk4[i];
            unsigned k0 = fkey(a.x * m.x), k1 = fkey(a.y * m.y);
            unsigned k2 = fkey(a.z * m.z), k3 = fkey(a.w * m.w);
            kmin = min(kmin, min(min(k0, k1), min(k2, k3)));
            kmax = max(kmax, max(max(k0, k1), max(k2, k3)));
            unsigned b;
            b = k0 >> 16; atomicAdd(&HIST[b >> 1], (b & 1) ? 65536u : 1u);
            b = k1 >> 16; atomicAdd(&HIST[b >> 1], (b & 1) ? 65536u : 1u);
            b = k2 >> 16; atomicAdd(&HIST[b >> 1], (b & 1) ? 65536u : 1u);
            b = k3 >> 16; atomicAdd(&HIST[b >> 1], (b & 1) ? 65536u : 1u);
        }
        #pragma unroll
        for (int o = 16; o; o >>= 1) {
            kmin = min(kmin, __shfl_down_sync(0xffffffffu, kmin, o));
            kmax = max(kmax, __shfl_down_sync(0xffffffffu, kmax, o));
        }
        if (lane == 0) { red[wz] = kmin; red[32 + wz] = kmax; }
    }
    __syncthreads();

    // ---------- setup: min/max, CDF->K, group sums ----------
    if (tid == 0) {
        unsigned mn = red[0], mx = red[32];
        for (int w = 1; w < 32; w++) { mn = min(mn, red[w]); mx = max(mx, red[32 + w]); }
        red[64] = mn; red[65] = mx;
    }
    if (tid == 32) {    // CDF -> K_j (sequential f32, matches reference)
        float s = 0.0f;
        for (int j = 0; j < 256; j++) { s += thist[c * 256 + j]; tgtT[j] = s; }
        float tot = s;
        for (int j = 0; j < 256; j++) {
            float t = (tgtT[j] / tot) * 262144.0f;
            float f = floorf(t);
            if (f < 0.0f) f = 0.0f;
            if (f > 262144.0f) f = 262144.0f;
            Karr[j] = (unsigned)f;
        }
    }
    if (tid >= 64 && tid < 320) {   // group sums
        int g = tid - 64;
        unsigned s = 0;
        for (int w = 0; w < 128; w++) {
            unsigned v = HIST[g * 128 + w];
            s += (v & 0xffffu) + (v >> 16);
        }
        sgrp[g] = s;
    }
    __syncthreads();
    if (tid == 0) {     // exclusive scan
        unsigned acc = 0;
        for (int g = 0; g < 256; g++) { unsigned t = sgrp[g]; sgrp[g] = acc; acc += t; }
        sgrp[256] = acc;
    }
    __syncthreads();

    // ---------- cut bin location + boundary key search ----------
    if (tid < 256) {
        unsigned k = Karr[tid];
        if (k == 0) { cutBin[tid] = 0xffffffffu; cutR[tid] = 0; }
        else {
            int lo = 0, hi = 255;
            while (lo < hi) { int mid = (lo + hi + 1) >> 1; if (sgrp[mid] < k) lo = mid; else hi = mid - 1; }
            unsigned acc = sgrp[lo];
            int bin = lo * 256;
            for (;; bin++) {
                unsigned w = HIST[bin >> 1];
                unsigned cnt = (bin & 1) ? (w >> 16) : (w & 0xffffu);
                if (acc + cnt >= k) break;
                acc += cnt;
            }
            cutBin[tid] = (unsigned)bin;
            cutR[tid] = k - acc;
        }
    } else if (tid < 511) {
        int j = tid - 255;          // 1..255
        unsigned mnk = red[64], mxk = red[65];
        float mn = dkey(mnk), mx = dkey(mxk);
        float dd = fmaxf(mx - mn, 1e-8f);
        if (binf(mxk, mn, dd) < j) kbA[j] = 0u;   // sentinel: no key reaches bin j
        else {
            unsigned lo = mnk, hi = mxk;
            while (lo < hi) {
                unsigned mid = lo + ((hi - lo) >> 1);
                if (binf(mid, mn, dd) >= j) hi = mid; else lo = mid + 1;
            }
            kbA[j] = lo;
        }
    }
    __syncthreads();

    // ---------- boundary prefix counts + merge active bins ----------
    if (tid >= 256 && tid < 511) {
        int j = tid - 255;
        unsigned kb = kbA[j];
        if (kb != 0u) {
            unsigned p = kb >> 16, g = p >> 8;
            unsigned s = sgrp[g];
            for (unsigned b = g << 8; b < p; b++) {
                unsigned w = HIST[b >> 1];
                s += (b & 1) ? (w >> 16) : (w & 0xffffu);
            }
            bPre[j] = s;
        }
    }
    if (tid == 0) {     // merge sorted cut bins + boundary prefixes (dedup)
        int i = 0, j = 1, n = 0;
        unsigned off = 0;
        for (;;) {
            unsigned a = 0xffffffffu, b = 0xffffffffu;
            while (i < 256 && cutBin[i] == 0xffffffffu) i++;
            if (i < 256) a = cutBin[i];
            while (j < 256 && kbA[j] == 0u) j++;
            if (j < 256) b = kbA[j] >> 16;
            if (a == 0xffffffffu && b == 0xffffffffu) break;
            unsigned v = min(a, b);
            while (i < 256 && cutBin[i] == v) i++;
            while (j < 256 && kbA[j] != 0u && (kbA[j] >> 16) == v) j++;
            unsigned w = HIST[v >> 1];
            unsigned cnt = (v & 1) ? (w >> 16) : (w & 0xffffu);
            uniqB[n] = v; segOff[n] = off; segLen[n] = cnt;
            off += cnt; n++;
        }
        red[66] = (unsigned)n;
    }
    __syncthreads();
    const int nU = (int)red[66];

    // ---------- slots, defaults, slot16 table ----------
    if (tid < 256) {
        thA[tid] = 0u;
        if (cutBin[tid] != 0xffffffffu) {
            unsigned p = cutBin[tid];
            int lo = 0, hi = nU - 1;
            while (lo < hi) { int mid = (lo + hi) >> 1; if (uniqB[mid] < p) lo = mid + 1; else hi = mid; }
            cutSlot[tid] = (unsigned)lo;
        }
    } else if (tid < 511) {
        int j = tid - 255;
        if (kbA[j] != 0u) {
            unsigned p = kbA[j] >> 16;
            int lo = 0, hi = nU - 1;
            while (lo < hi) { int mid = (lo + hi) >> 1; if (uniqB[mid] < p) lo = mid + 1; else hi = mid; }
            bSlot[j] = (unsigned)lo;
        }
    }
    if (tid < 257) rankA[tid] = (tid == 0) ? 0u : (unsigned)HW;
    if (tid < 512) cursor[tid] = 0;
    __syncthreads();
    for (int i = tid; i < 32768; i += NT) HIST[i] = 0xffffffffu;  // slot16 = inactive
    __syncthreads();
    if (tid < nU) ((unsigned short*)HIST)[uniqB[tid]] = (unsigned short)tid;
    __syncthreads();

    // ---------- Pass 2: compaction of candidates into per-bin segments ----------
    {
        const unsigned short* slot16 = (const unsigned short*)HIST;
        for (int i = tid; i < HW / 4; i += NT) {
            float4 a = in4[i], m = mk4[i];
            unsigned k0 = fkey(a.x * m.x), k1 = fkey(a.y * m.y);
            unsigned k2 = fkey(a.z * m.z), k3 = fkey(a.w * m.w);
            unsigned s;
            s = slot16[k0 >> 16];
            if (s != 0xffffu) candC[segOff[s] + atomicAdd(&cursor[s], 1u)] = k0;
            s = slot16[k1 >> 16];
            if (s != 0xffffu) candC[segOff[s] + atomicAdd(&cursor[s], 1u)] = k1;
            s = slot16[k2 >> 16];
            if (s != 0xffffu) candC[segOff[s] + atomicAdd(&cursor[s], 1u)] = k2;
            s = slot16[k3 >> 16];
            if (s != 0xffffu) candC[segOff[s] + atomicAdd(&cursor[s], 1u)] = k3;
        }
    }
    __syncthreads();

    // ---------- Phase D: resolve queries on candidate segments (warp per query) ----------
    {
        unsigned* wh = WH + wz * 256;
        for (int q = wz; q < 511; q += 32) {
            if (q < 256) {
                if (cutBin[q] == 0xffffffffu) continue;
                unsigned slot = cutSlot[q];
                unsigned off = segOff[slot], len = segLen[slot], r = cutR[q];
                // round A: high byte of 16-bit suffix
                for (int i = lane; i < 256; i += 32) wh[i] = 0;
                __syncwarp();
                for (unsigned i = lane; i < len; i += 32)
                    atomicAdd(&wh[(candC[off + i] >> 8) & 0xffu], 1u);
                __syncwarp();
                unsigned hi8 = 0, rem = 0;
                if (lane == 0) {
                    unsigned acc = 0; int b = 0;
                    for (;; b++) { unsigned ct = wh[b]; if (acc + ct >= r) break; acc += ct; }
                    hi8 = (unsigned)b; rem = r - acc;
                }
                hi8 = __shfl_sync(0xffffffffu, hi8, 0);
                rem = __shfl_sync(0xffffffffu, rem, 0);
                // round B: low byte
                for (int i = lane; i < 256; i += 32) wh[i] = 0;
                __syncwarp();
                for (unsigned i = lane; i < len; i += 32) {
                    unsigned sfx = candC[off + i] & 0xffffu;
                    if ((sfx >> 8) == hi8) atomicAdd(&wh[sfx & 0xffu], 1u);
                }
                __syncwarp();
                if (lane == 0) {
                    unsigned acc = 0; int b = 0;
                    for (;; b++) { unsigned ct = wh[b]; if (acc + ct >= rem) break; acc += ct; }
                    thA[q] = (cutBin[q] << 16) | (hi8 << 8) | (unsigned)b;
                }
                __syncwarp();
            } else {
                int j = q - 255;
                if (kbA[j] == 0u) continue;
                unsigned slot = bSlot[j];
                unsigned off = segOff[slot], len = segLen[slot];
                unsigned bs = kbA[j] & 0xffffu;
                unsigned cnt = 0;
                for (unsigned i = lane; i < len; i += 32)
                    cnt += ((candC[off + i] & 0xffffu) < bs) ? 1u : 0u;
                #pragma unroll
                for (int o = 16; o; o >>= 1) cnt += __shfl_down_sync(0xffffffffu, cnt, o);
                if (lane == 0) rankA[j] = bPre[j] + cnt;
            }
        }
    }
    __syncthreads();

    // ---------- Phase E: cur_hist (analytic), target table, bm lookup table ----------
    if (tid < 256) {
        out[1 + c * 256 + tid] = (float)(rankA[tid + 1] - rankA[tid]);
        float tmn = tmin_[c];
        float scl = tmax_[c] - tmn;
        tgtT[tid] = ((float)tid / 255.0f) * scl + tmn;
    }
    {
        // tb16[p]: if no threshold has prefix p -> bm directly; else 0x8000|firstIdx
        int p0 = tid * 64;
        unsigned keylim = (unsigned)p0 << 16;
        int lo = 0, hi = 256;
        while (lo < hi) { int mid = (lo + hi) >> 1; if (thA[mid] < keylim) lo = mid + 1; else hi = mid; }
        int idx = lo;
        #pragma unroll 4
        for (int w = 0; w < 32; w++) {
            unsigned word = 0;
            #pragma unroll
            for (int e = 0; e < 2; e++) {
                int p = p0 + w * 2 + e;
                while (idx < 256 && (int)(thA[idx] >> 16) < p) idx++;
                unsigned v;
                if (idx < 256 && (int)(thA[idx] >> 16) == p) v = 0x8000u | (unsigned)idx;
                else v = (unsigned)min(idx, 255);
                word |= v << (16 * e);
            }
            // NOTE: writes into HIST region — slot16 no longer needed
            WH[0] = WH[0]; // no-op fence avoidance placeholder removed by compiler
            HIST[(p0 >> 1) + w] = word;
        }
    }
    // cache scalars before reusing red region semantics (no overwrite of red here)
    const float mnF = dkey(red[64]);
    const float mxF = dkey(red[65]);
    __syncthreads();

    // ---------- Pass 3: loss ----------
    {
        const unsigned short* tb16 = (const unsigned short*)HIST;
        float acc = 0.0f;
        for (int i = tid; i < HW / 4; i += NT) {
            float4 a = in4[i], m = mk4[i];
            float vv[4] = {a.x * m.x, a.y * m.y, a.z * m.z, a.w * m.w};
            #pragma unroll
            for (int e = 0; e < 4; e++) {
                float v = vv[e];
                unsigned key = fkey(v);
                unsigned t = tb16[key >> 16];
                unsigned bm;
                if (t & 0x8000u) {
                    unsigned idx = t & 0x7fffu;
                    while (idx < 256u && thA[idx] < key) idx++;
                    bm = min(idx, 255u);
                } else bm = t;
                float df = v - tgtT[bm];
                acc = fmaf(df, df, acc);
            }
        }
        #pragma unroll
        for (int o = 16; o; o >>= 1) acc += __shfl_down_sync(0xffffffffu, acc, o);
        float* fred = (float*)uniqB;     // free after phase D
        if (lane == 0) fred[wz] = acc;
        __syncthreads();
        if (tid == 0) {
            float s = 0.0f;
            for (int w = 0; w < 32; w++) s += fred[w];
            atomicAdd(&g_loss, (double)s);
            out[1 + 32768 + c]       = mnF;
            out[1 + 32768 + 128 + c] = mxF;
        }
    }
}

extern "C" void kernel_launch(void* const* d_in, const int* in_sizes, int n_in,
                              void* d_out, int out_size)
{
    const float* input = (const float*)d_in[0];
    const float* mask  = (const float*)d_in[1];
    const float* thist = (const float*)d_in[2];
    const float* tmn   = (const float*)d_in[3];
    const float* tmx   = (const float*)d_in[4];
    float* out = (float*)d_out;

    cudaFuncSetAttribute(main_kernel, cudaFuncAttributeMaxDynamicSharedMemorySize, SMEM_BYTES);

    init_kernel<<<1, 1>>>();
    main_kernel<<<CCH, 1024, SMEM_BYTES>>>(input, mask, thist, tmn, tmx, out);
    finish_kernel<<<1, 1>>>(out);
}